// round 3
// baseline (speedup 1.0000x reference)
#include <cuda_runtime.h>
#include <math.h>

#define B_DIM 64
#define D_DIM 65536
#define S_SL  8                       // slices per row in pass 1
#define NTA   512                     // pass-1 block size
#define SLICE (D_DIM / S_SL)          // 8192 elements per slice
#define PAIRS_T (SLICE / 2 / NTA)     // 8 float2-pairs per thread
#define NTB   1024                    // select block size
#define CAP   8192                    // shared candidate list capacity (32KB)

// ---- __device__ global scratch (allocation-free) ----
__device__ unsigned g_keys[B_DIM * D_DIM];        // 16MB: monotone key per element
__device__ unsigned g_hist[B_DIM * S_SL * 256];   // per-CTA 256-bin histograms
__device__ float    g_sl_loc[B_DIM * S_SL];
__device__ float    g_sl_bce[B_DIM * S_SL];
__device__ int      g_sl_pos[B_DIM * S_SL];
__device__ float    g_row_loc[B_DIM];
__device__ float    g_row_conf[B_DIM];
__device__ int      g_row_pos[B_DIM];
__device__ int      g_row_sel[B_DIM];

__device__ __forceinline__ float softplus_f(float x) {
    return fmaxf(x, 0.0f) + log1pf(expf(-fabsf(x)));
}
__device__ __forceinline__ float sl1f(float d) {
    float ad = fabsf(d);
    return (ad < 1.0f) ? 0.5f * d * d : (ad - 0.5f);
}
// Monotone key: order(key) == order(float). Positives are stored as key==0,
// which ranks below every finite negative's key.
__device__ __forceinline__ unsigned key_of(float x) {
    unsigned u = __float_as_uint(x);
    return (u & 0x80000000u) ? ~u : (u | 0x80000000u);
}
__device__ __forceinline__ float val_of_key(unsigned k) {
    unsigned u = (k & 0x80000000u) ? (k & 0x7FFFFFFFu) : ~k;
    return __uint_as_float(u);
}

// Block sum via shuffles + one shared line. nwarp = blockDim/32.
template<int NWARP>
__device__ __forceinline__ float blk_sum(float v, float* red, int t) {
    #pragma unroll
    for (int o = 16; o > 0; o >>= 1) v += __shfl_down_sync(0xFFFFFFFFu, v, o);
    if ((t & 31) == 0) red[t >> 5] = v;
    __syncthreads();
    if (t < 32) {
        float w = (t < NWARP) ? red[t] : 0.0f;
        #pragma unroll
        for (int o = 16; o > 0; o >>= 1) w += __shfl_down_sync(0xFFFFFFFFu, w, o);
        if (t == 0) red[0] = w;
    }
    __syncthreads();
    float r = red[0];
    __syncthreads();
    return r;
}

// Warp-cooperative descending select over a 256-bin histogram.
// Requires 0 < k <= total(h). Returns bin, *rem = # of elements == bin needed.
// Call with t = lane (threads 0..31); all lanes get the same result.
__device__ __forceinline__ int warp_select(const unsigned* h, int k, int lane, int* rem_out) {
    int s = 0;
    #pragma unroll
    for (int m = 0; m < 8; m++) s += (int)h[255 - lane * 8 - m];
    int inc = s;
    #pragma unroll
    for (int o = 1; o < 32; o <<= 1) {
        int v = __shfl_up_sync(0xFFFFFFFFu, inc, o);
        if (lane >= o) inc += v;
    }
    int pre = inc - s;   // exclusive prefix (bins above this lane's chunk)
    unsigned m = __ballot_sync(0xFFFFFFFFu, (pre < k) && (pre + s >= k));
    int chosen = __ffs(m) - 1;
    int bin = 0, rem = 0;
    if (lane == chosen) {
        int acc = pre;
        int hi = 255 - lane * 8;
        #pragma unroll
        for (int b = 0; b < 8; b++) {
            int c = (int)h[hi - b];
            if (acc + c >= k) { bin = hi - b; rem = k - acc; break; }
            acc += c;
        }
    }
    bin = __shfl_sync(0xFFFFFFFFu, bin, chosen);
    rem = __shfl_sync(0xFFFFFFFFu, rem, chosen);
    *rem_out = rem;
    return bin;
}

// ---------------- Pass 1: stats + keys + top-8-bit histogram ----------------
__global__ void __launch_bounds__(NTA) mbl_pass1(
    const float4* __restrict__ loc_data,
    const float2* __restrict__ conf2,
    const float4* __restrict__ loc_t,
    const int2*   __restrict__ ct2)
{
    __shared__ unsigned wh[16][256];   // warp-private histograms (16KB)
    __shared__ float red[16];

    const int t = threadIdx.x, w = t >> 5;
    const int row = blockIdx.x / S_SL, sl = blockIdx.x % S_SL;

    for (int i = t; i < 16 * 256; i += NTA) ((unsigned*)wh)[i] = 0;
    __syncthreads();

    const size_t pq0 = (size_t)row * (D_DIM / 2) + (size_t)sl * (SLICE / 2);
    float npos = 0.0f, pb = 0.0f, ls = 0.0f;

    #pragma unroll
    for (int j = 0; j < PAIRS_T; j++) {
        size_t q = pq0 + t + j * NTA;      // pair index (global)
        float2 x = conf2[q];
        int2   c = ct2[q];
        size_t e = 2 * q;                   // element index (global)
        unsigned k0 = 0u, k1 = 0u;
        if (c.x > 0) {
            npos += 1.0f; pb += softplus_f(-x.x);
            float4 a = loc_data[e], b = loc_t[e];
            ls += sl1f(a.x - b.x) + sl1f(a.y - b.y) + sl1f(a.z - b.z) + sl1f(a.w - b.w);
        } else {
            k0 = key_of(x.x);
            atomicAdd(&wh[w][k0 >> 24], 1u);
        }
        if (c.y > 0) {
            npos += 1.0f; pb += softplus_f(-x.y);
            float4 a = loc_data[e + 1], b = loc_t[e + 1];
            ls += sl1f(a.x - b.x) + sl1f(a.y - b.y) + sl1f(a.z - b.z) + sl1f(a.w - b.w);
        } else {
            k1 = key_of(x.y);
            atomicAdd(&wh[w][k1 >> 24], 1u);
        }
        reinterpret_cast<uint2*>(g_keys)[q] = make_uint2(k0, k1);
    }
    __syncthreads();

    for (int b = t; b < 256; b += NTA) {
        unsigned s = 0;
        #pragma unroll
        for (int m = 0; m < 16; m++) s += wh[m][b];
        g_hist[blockIdx.x * 256 + b] = s;
    }

    float npos_r = blk_sum<16>(npos, red, t);
    float ls_r   = blk_sum<16>(ls,   red, t);
    float pb_r   = blk_sum<16>(pb,   red, t);
    if (t == 0) {
        g_sl_pos[blockIdx.x] = (int)npos_r;
        g_sl_loc[blockIdx.x] = ls_r;
        g_sl_bce[blockIdx.x] = pb_r;
    }
}

// ---------------- Pass 2: per-row select + conf-loss sum ----------------
__global__ void __launch_bounds__(NTB) mbl_select()
{
    __shared__ unsigned h0[256];
    __shared__ unsigned rh[256];
    __shared__ unsigned list[CAP];
    __shared__ float    red[32];
    __shared__ int      sh_nlist, sh_b8, sh_rem, sh_bin2, sh_rem2;
    __shared__ int      sh_npos, sh_k;
    __shared__ float    sh_pb, sh_ls;

    const int t = threadIdx.x;
    const int row = blockIdx.x;

    if (t < 256) {
        unsigned s = 0;
        #pragma unroll
        for (int m = 0; m < S_SL; m++) s += g_hist[(row * S_SL + m) * 256 + t];
        h0[t] = s;
    }
    if (t == 0) {
        int np = 0; float pb = 0.0f, ls = 0.0f;
        #pragma unroll
        for (int m = 0; m < S_SL; m++) {
            np += g_sl_pos[row * S_SL + m];
            pb += g_sl_bce[row * S_SL + m];
            ls += g_sl_loc[row * S_SL + m];
        }
        sh_npos = np; sh_pb = pb; sh_ls = ls;
        sh_k = min(3 * np, D_DIM);
        sh_nlist = 0;
    }
    __syncthreads();
    const int k = sh_k;

    if (t < 32) {
        if (k > 0) {
            int rem; int bin = warp_select(h0, k, t, &rem);
            if (t == 0) { sh_b8 = bin; sh_rem = rem; }
        } else if (t == 0) { sh_b8 = 300; sh_rem = 0; }
    }
    __syncthreads();
    const unsigned b8 = (unsigned)sh_b8;

    // Single scan of this row's keys (L2-resident).
    const uint4* kp = reinterpret_cast<const uint4*>(g_keys + (size_t)row * D_DIM);
    float csum = 0.0f;
    #pragma unroll 2
    for (int j = 0; j < D_DIM / 4 / NTB; j++) {   // 16 iterations
        uint4 kv = kp[t + j * NTB];
        unsigned ks[4] = {kv.x, kv.y, kv.z, kv.w};
        #pragma unroll
        for (int h = 0; h < 4; h++) {
            unsigned kk = ks[h];
            if (kk == 0u) continue;                 // positive (or padding)
            unsigned tb = kk >> 24;
            if (tb > b8) {
                csum += softplus_f(val_of_key(kk)); // strictly selected
            } else if (tb == b8) {
                int p = atomicAdd(&sh_nlist, 1);
                if (p < CAP) list[p] = kk;
            }
        }
    }
    __syncthreads();

    const int nlist = sh_nlist;
    unsigned prefix = b8;
    int rem = sh_rem;
    unsigned T = 0u; int req = 0;

    if (sh_b8 <= 255) {
        if (nlist <= CAP) {
            // ---- in-shared exact refine over 3 more 8-bit levels ----
            #pragma unroll
            for (int lvl = 0; lvl < 3; lvl++) {
                if (t < 256) rh[t] = 0;
                __syncthreads();
                const int mm = 24 - 8 * lvl;   // prefix-match shift
                const int sm = 16 - 8 * lvl;   // bin shift
                for (int p = t; p < nlist; p += NTB) {
                    unsigned kk = list[p];
                    if ((kk >> mm) == prefix)
                        atomicAdd(&rh[(kk >> sm) & 255u], 1u);
                }
                __syncthreads();
                if (t < 32) {
                    int r2; int b = warp_select(rh, rem, t, &r2);
                    if (t == 0) { sh_bin2 = b; sh_rem2 = r2; }
                }
                __syncthreads();
                prefix = (prefix << 8) | (unsigned)sh_bin2;
                rem = sh_rem2;
                __syncthreads();
            }
            T = prefix; req = rem;
            for (int p = t; p < nlist; p += NTB) {
                unsigned kk = list[p];
                if (kk > T) csum += softplus_f(val_of_key(kk));
            }
        } else {
            // ---- fallback: global rescans (rare/pathological) ----
            for (int lvl = 0; lvl < 3; lvl++) {
                if (t < 256) rh[t] = 0;
                __syncthreads();
                const int mm = 24 - 8 * lvl;
                const int sm = 16 - 8 * lvl;
                for (int j = 0; j < D_DIM / 4 / NTB; j++) {
                    uint4 kv = kp[t + j * NTB];
                    unsigned ks[4] = {kv.x, kv.y, kv.z, kv.w};
                    #pragma unroll
                    for (int h = 0; h < 4; h++) {
                        unsigned kk = ks[h];
                        if (kk != 0u && (kk >> mm) == prefix)
                            atomicAdd(&rh[(kk >> sm) & 255u], 1u);
                    }
                }
                __syncthreads();
                if (t < 32) {
                    int r2; int b = warp_select(rh, rem, t, &r2);
                    if (t == 0) { sh_bin2 = b; sh_rem2 = r2; }
                }
                __syncthreads();
                prefix = (prefix << 8) | (unsigned)sh_bin2;
                rem = sh_rem2;
                __syncthreads();
            }
            T = prefix; req = rem;
            for (int j = 0; j < D_DIM / 4 / NTB; j++) {
                uint4 kv = kp[t + j * NTB];
                unsigned ks[4] = {kv.x, kv.y, kv.z, kv.w};
                #pragma unroll
                for (int h = 0; h < 4; h++) {
                    unsigned kk = ks[h];
                    if (kk != 0u && (kk >> 24) == b8 && kk > T)
                        csum += softplus_f(val_of_key(kk));
                }
            }
        }
    }
    __syncthreads();

    float csum_row = blk_sum<32>(csum, red, t);
    if (t == 0) {
        float tv = (req > 0 && T != 0u) ? softplus_f(val_of_key(T)) : 0.0f;
        g_row_conf[row] = sh_pb + csum_row + (float)req * tv;
        g_row_loc[row]  = sh_ls;
        g_row_pos[row]  = sh_npos;
        g_row_sel[row]  = sh_npos + k;
    }
}

// ---------------- Final reduction across rows ----------------
__global__ void mbl_fin(float* out) {
    int t = threadIdx.x;   // 64 threads
    float lc = g_row_loc[t], cf = g_row_conf[t];
    float ps = (float)g_row_pos[t], sl = (float)g_row_sel[t];
    #pragma unroll
    for (int o = 16; o > 0; o >>= 1) {
        lc += __shfl_down_sync(0xFFFFFFFFu, lc, o);
        cf += __shfl_down_sync(0xFFFFFFFFu, cf, o);
        ps += __shfl_down_sync(0xFFFFFFFFu, ps, o);
        sl += __shfl_down_sync(0xFFFFFFFFu, sl, o);
    }
    __shared__ float sh[8];
    if ((t & 31) == 0) {
        int w = t >> 5;
        sh[w * 4 + 0] = lc; sh[w * 4 + 1] = cf; sh[w * 4 + 2] = ps; sh[w * 4 + 3] = sl;
    }
    __syncthreads();
    if (t == 0) {
        lc = sh[0] + sh[4]; cf = sh[1] + sh[5];
        ps = sh[2] + sh[6]; sl = sh[3] + sh[7];
        out[0] = lc / (4.0f * ps) / ps;
        out[1] = cf / sl / ps;
    }
}

extern "C" void kernel_launch(void* const* d_in, const int* in_sizes, int n_in,
                              void* d_out, int out_size)
{
    const float4* loc_data  = nullptr;
    const float4* loc_tgt   = nullptr;
    const float2* conf_data = nullptr;
    const int2*   conf_tgt  = nullptr;
    for (int i = 0; i < n_in; i++) {
        if (in_sizes[i] == B_DIM * D_DIM * 4) {
            if (!loc_data) loc_data = (const float4*)d_in[i];
            else           loc_tgt  = (const float4*)d_in[i];
        } else {
            if (!conf_data) conf_data = (const float2*)d_in[i];
            else            conf_tgt  = (const int2*)d_in[i];
        }
    }

    mbl_pass1<<<B_DIM * S_SL, NTA>>>(loc_data, conf_data, loc_tgt, conf_tgt);
    mbl_select<<<B_DIM, NTB>>>();
    mbl_fin<<<1, 64>>>((float*)d_out);
}

// round 4
// speedup vs baseline: 1.4243x; 1.4243x over previous
#include <cuda_runtime.h>
#include <math.h>

#define B_DIM 64
#define D_DIM 65536
#define S_SL  8                       // slices per row in pass 1
#define NTA   512                     // pass-1 block size
#define SLICE (D_DIM / S_SL)          // 8192 elements
#define PAIRS_T (SLICE / 2 / NTA)     // 8 float2-pairs per thread
#define NTB   1024                    // select block size
#define CAP   4096                    // shared candidate list (16KB)
#define NBIN  4096                    // 12-bit level-1 bins

// ---- __device__ global scratch (allocation-free) ----
__device__ unsigned g_keys[B_DIM * D_DIM];     // 16MB monotone keys
__device__ unsigned g_hcnt[B_DIM * NBIN];      // per-row 12-bit histogram
                                               // (BSS-zero; select re-zeroes after use)
__device__ float    g_sl_loc[B_DIM * S_SL];
__device__ float    g_sl_bce[B_DIM * S_SL];
__device__ int      g_sl_pos[B_DIM * S_SL];
__device__ float    g_row_loc[B_DIM];
__device__ float    g_row_conf[B_DIM];
__device__ int      g_row_pos[B_DIM];
__device__ int      g_row_sel[B_DIM];

__device__ __forceinline__ float softplus_f(float x) {
    return fmaxf(x, 0.0f) + log1pf(expf(-fabsf(x)));
}
__device__ __forceinline__ float sl1f(float d) {
    float ad = fabsf(d);
    return (ad < 1.0f) ? 0.5f * d * d : (ad - 0.5f);
}
__device__ __forceinline__ unsigned key_of(float x) {
    unsigned u = __float_as_uint(x);
    return (u & 0x80000000u) ? ~u : (u | 0x80000000u);
}
__device__ __forceinline__ float val_of_key(unsigned k) {
    unsigned u = (k & 0x80000000u) ? (k & 0x7FFFFFFFu) : ~k;
    return __uint_as_float(u);
}

template<int NWARP>
__device__ __forceinline__ float blk_sum(float v, float* red, int t) {
    #pragma unroll
    for (int o = 16; o > 0; o >>= 1) v += __shfl_down_sync(0xFFFFFFFFu, v, o);
    if ((t & 31) == 0) red[t >> 5] = v;
    __syncthreads();
    if (t < 32) {
        float w = (t < NWARP) ? red[t] : 0.0f;
        #pragma unroll
        for (int o = 16; o > 0; o >>= 1) w += __shfl_down_sync(0xFFFFFFFFu, w, o);
        if (t == 0) red[0] = w;
    }
    __syncthreads();
    float r = red[0];
    __syncthreads();
    return r;
}

// Warp-cooperative descending select over a 256-bin histogram (lanes 0..31).
__device__ __forceinline__ int warp_select(const unsigned* h, int k, int lane, int* rem_out) {
    int s = 0;
    #pragma unroll
    for (int m = 0; m < 8; m++) s += (int)h[255 - lane * 8 - m];
    int inc = s;
    #pragma unroll
    for (int o = 1; o < 32; o <<= 1) {
        int v = __shfl_up_sync(0xFFFFFFFFu, inc, o);
        if (lane >= o) inc += v;
    }
    int pre = inc - s;
    unsigned m = __ballot_sync(0xFFFFFFFFu, (pre < k) && (pre + s >= k));
    int chosen = __ffs(m) - 1;
    int bin = 0, rem = 0;
    if (lane == chosen) {
        int acc = pre, hi = 255 - lane * 8;
        #pragma unroll
        for (int b = 0; b < 8; b++) {
            int c = (int)h[hi - b];
            if (acc + c >= k) { bin = hi - b; rem = k - acc; break; }
            acc += c;
        }
    }
    bin = __shfl_sync(0xFFFFFFFFu, bin, chosen);
    rem = __shfl_sync(0xFFFFFFFFu, rem, chosen);
    *rem_out = rem;
    return bin;
}

// ---------------- Pass 1: stats + keys + 12-bit histogram ----------------
__global__ void __launch_bounds__(NTA) mbl_pass1(
    const float4* __restrict__ loc_data,
    const float2* __restrict__ conf2,
    const float4* __restrict__ loc_t,
    const int2*   __restrict__ ct2)
{
    __shared__ unsigned shc[NBIN];   // 16KB, single copy, shared atomics
    __shared__ float red[16];

    const int t = threadIdx.x;
    const int row = blockIdx.x / S_SL, sl = blockIdx.x % S_SL;

    for (int i = t; i < NBIN; i += NTA) shc[i] = 0;
    __syncthreads();

    const size_t pq0 = (size_t)row * (D_DIM / 2) + (size_t)sl * (SLICE / 2);
    float npos = 0.0f, pb = 0.0f, ls = 0.0f;

    #pragma unroll
    for (int half = 0; half < 2; half++) {
        // batched loads for MLP
        float2 xv[4]; int2 cv[4];
        #pragma unroll
        for (int j = 0; j < 4; j++) {
            size_t q = pq0 + t + (size_t)(half * 4 + j) * NTA;
            xv[j] = conf2[q];
            cv[j] = ct2[q];
        }
        #pragma unroll
        for (int j = 0; j < 4; j++) {
            size_t q = pq0 + t + (size_t)(half * 4 + j) * NTA;
            size_t e = 2 * q;
            unsigned k0 = 0u, k1 = 0u;
            if (cv[j].x > 0) {
                npos += 1.0f; pb += softplus_f(-xv[j].x);
                float4 a = loc_data[e], b = loc_t[e];
                ls += sl1f(a.x - b.x) + sl1f(a.y - b.y) + sl1f(a.z - b.z) + sl1f(a.w - b.w);
            } else {
                k0 = key_of(xv[j].x);
                atomicAdd(&shc[k0 >> 20], 1u);
            }
            if (cv[j].y > 0) {
                npos += 1.0f; pb += softplus_f(-xv[j].y);
                float4 a = loc_data[e + 1], b = loc_t[e + 1];
                ls += sl1f(a.x - b.x) + sl1f(a.y - b.y) + sl1f(a.z - b.z) + sl1f(a.w - b.w);
            } else {
                k1 = key_of(xv[j].y);
                atomicAdd(&shc[k1 >> 20], 1u);
            }
            reinterpret_cast<uint2*>(g_keys)[q] = make_uint2(k0, k1);
        }
    }

    float npos_r = blk_sum<16>(npos, red, t);
    float ls_r   = blk_sum<16>(ls,   red, t);
    float pb_r   = blk_sum<16>(pb,   red, t);
    if (t == 0) {
        g_sl_pos[blockIdx.x] = (int)npos_r;
        g_sl_loc[blockIdx.x] = ls_r;
        g_sl_bce[blockIdx.x] = pb_r;
    }
    __syncthreads();

    // flush nonzero bins to the per-row global histogram
    for (int b = t; b < NBIN; b += NTA) {
        unsigned c = shc[b];
        if (c) atomicAdd(&g_hcnt[row * NBIN + b], c);
    }
}

// ---------------- Pass 2: per-row select + conf-loss sum ----------------
__global__ void __launch_bounds__(NTB) mbl_select()
{
    __shared__ unsigned hc[NBIN];     // 16KB
    __shared__ int      s1[NTB];      // 4KB chunk sums
    __shared__ int      s2[32];
    __shared__ unsigned rh[256];
    __shared__ unsigned list[CAP];    // 16KB
    __shared__ float    red[32];
    __shared__ int      sh_b12, sh_rem, sh_nlist, sh_bin2, sh_rem2;
    __shared__ int      sh_npos, sh_k;
    __shared__ float    sh_pb, sh_ls;

    const int t = threadIdx.x;
    const int row = blockIdx.x;

    // load per-row histogram, zero the global copy for the next launch
    #pragma unroll
    for (int j = 0; j < NBIN / NTB; j++) {
        int b = t + j * NTB;
        hc[b] = g_hcnt[row * NBIN + b];
        g_hcnt[row * NBIN + b] = 0u;
    }
    if (t == 0) {
        int np = 0; float pb = 0.0f, ls = 0.0f;
        #pragma unroll
        for (int m = 0; m < S_SL; m++) {
            np += g_sl_pos[row * S_SL + m];
            pb += g_sl_bce[row * S_SL + m];
            ls += g_sl_loc[row * S_SL + m];
        }
        sh_npos = np; sh_pb = pb; sh_ls = ls;
        sh_k = min(3 * np, D_DIM);
        sh_nlist = 0;
    }
    __syncthreads();
    const int k = sh_k;

    // hierarchical descending select over 4096 bins
    s1[t] = (int)hc[4*t] + (int)hc[4*t+1] + (int)hc[4*t+2] + (int)hc[4*t+3];
    __syncthreads();
    {
        int s = s1[t];
        #pragma unroll
        for (int o = 16; o > 0; o >>= 1) s += __shfl_down_sync(0xFFFFFFFFu, s, o);
        if ((t & 31) == 0) s2[t >> 5] = s;
    }
    __syncthreads();
    if (t == 0) {
        if (k > 0) {
            int acc = 0, seg = 0;
            for (int w = 31; w >= 0; w--) {
                if (acc + s2[w] >= k) { seg = w; break; }
                acc += s2[w];
            }
            int ch = seg * 32;
            for (int c = 31; c >= 0; c--) {
                int idx = seg * 32 + c;
                if (acc + s1[idx] >= k) { ch = idx; break; }
                acc += s1[idx];
            }
            int bin = ch * 4;
            for (int b = 3; b >= 0; b--) {
                int idx = ch * 4 + b;
                if (acc + (int)hc[idx] >= k) { bin = idx; break; }
                acc += (int)hc[idx];
            }
            sh_b12 = bin; sh_rem = k - acc;
        } else { sh_b12 = NBIN + 1; sh_rem = 0; }
    }
    __syncthreads();
    const unsigned b12 = (unsigned)sh_b12;

    // one scan of this row's keys (L2-resident)
    const uint4* kp = reinterpret_cast<const uint4*>(g_keys + (size_t)row * D_DIM);
    float csum = 0.0f;
    #pragma unroll 4
    for (int j = 0; j < D_DIM / 4 / NTB; j++) {   // 16 iterations
        uint4 kv = kp[t + j * NTB];
        unsigned ks[4] = {kv.x, kv.y, kv.z, kv.w};
        #pragma unroll
        for (int h = 0; h < 4; h++) {
            unsigned kk = ks[h];
            if (kk == 0u) continue;
            unsigned tb = kk >> 20;
            if (tb > b12) {
                csum += softplus_f(val_of_key(kk));
            } else if (tb == b12) {
                int p = atomicAdd(&sh_nlist, 1);
                if (p < CAP) list[p] = kk;
            }
        }
    }
    __syncthreads();

    const int nlist = sh_nlist;
    unsigned prefix = b12;
    int rem = sh_rem;
    unsigned T = 0u; int req = 0;

    const int MM[3] = {20, 12, 4};   // prefix-match shifts
    const int SB[3] = {12, 4, 0};    // bin shifts
    const unsigned MK[3] = {255u, 255u, 15u};

    if (k > 0) {
        if (nlist <= CAP) {
            #pragma unroll
            for (int lvl = 0; lvl < 3; lvl++) {
                if (t < 256) rh[t] = 0;
                __syncthreads();
                for (int p = t; p < nlist; p += NTB) {
                    unsigned kk = list[p];
                    if ((kk >> MM[lvl]) == prefix)
                        atomicAdd(&rh[(kk >> SB[lvl]) & MK[lvl]], 1u);
                }
                __syncthreads();
                if (t < 32) {
                    int r2; int b = warp_select(rh, rem, t, &r2);
                    if (t == 0) { sh_bin2 = b; sh_rem2 = r2; }
                }
                __syncthreads();
                prefix = (prefix << ((lvl == 2) ? 4 : 8)) | (unsigned)sh_bin2;
                rem = sh_rem2;
                __syncthreads();
            }
            T = prefix; req = rem;
            for (int p = t; p < nlist; p += NTB) {
                unsigned kk = list[p];
                if (kk > T) csum += softplus_f(val_of_key(kk));
            }
        } else {
            // fallback: refine via global rescans (should be ~never taken now)
            for (int lvl = 0; lvl < 3; lvl++) {
                if (t < 256) rh[t] = 0;
                __syncthreads();
                for (int j = 0; j < D_DIM / 4 / NTB; j++) {
                    uint4 kv = kp[t + j * NTB];
                    unsigned ks[4] = {kv.x, kv.y, kv.z, kv.w};
                    #pragma unroll
                    for (int h = 0; h < 4; h++) {
                        unsigned kk = ks[h];
                        if (kk != 0u && (kk >> MM[lvl]) == prefix)
                            atomicAdd(&rh[(kk >> SB[lvl]) & MK[lvl]], 1u);
                    }
                }
                __syncthreads();
                if (t < 32) {
                    int r2; int b = warp_select(rh, rem, t, &r2);
                    if (t == 0) { sh_bin2 = b; sh_rem2 = r2; }
                }
                __syncthreads();
                prefix = (prefix << ((lvl == 2) ? 4 : 8)) | (unsigned)sh_bin2;
                rem = sh_rem2;
                __syncthreads();
            }
            T = prefix; req = rem;
            for (int j = 0; j < D_DIM / 4 / NTB; j++) {
                uint4 kv = kp[t + j * NTB];
                unsigned ks[4] = {kv.x, kv.y, kv.z, kv.w};
                #pragma unroll
                for (int h = 0; h < 4; h++) {
                    unsigned kk = ks[h];
                    if (kk != 0u && (kk >> 20) == b12 && kk > T)
                        csum += softplus_f(val_of_key(kk));
                }
            }
        }
    }
    __syncthreads();

    float csum_row = blk_sum<32>(csum, red, t);
    if (t == 0) {
        float tv = (req > 0 && T != 0u) ? softplus_f(val_of_key(T)) : 0.0f;
        g_row_conf[row] = sh_pb + csum_row + (float)req * tv;
        g_row_loc[row]  = sh_ls;
        g_row_pos[row]  = sh_npos;
        g_row_sel[row]  = sh_npos + k;
    }
}

// ---------------- Final reduction across rows ----------------
__global__ void mbl_fin(float* out) {
    int t = threadIdx.x;   // 64 threads
    float lc = g_row_loc[t], cf = g_row_conf[t];
    float ps = (float)g_row_pos[t], sl = (float)g_row_sel[t];
    #pragma unroll
    for (int o = 16; o > 0; o >>= 1) {
        lc += __shfl_down_sync(0xFFFFFFFFu, lc, o);
        cf += __shfl_down_sync(0xFFFFFFFFu, cf, o);
        ps += __shfl_down_sync(0xFFFFFFFFu, ps, o);
        sl += __shfl_down_sync(0xFFFFFFFFu, sl, o);
    }
    __shared__ float sh[8];
    if ((t & 31) == 0) {
        int w = t >> 5;
        sh[w * 4 + 0] = lc; sh[w * 4 + 1] = cf; sh[w * 4 + 2] = ps; sh[w * 4 + 3] = sl;
    }
    __syncthreads();
    if (t == 0) {
        lc = sh[0] + sh[4]; cf = sh[1] + sh[5];
        ps = sh[2] + sh[6]; sl = sh[3] + sh[7];
        out[0] = lc / (4.0f * ps) / ps;
        out[1] = cf / sl / ps;
    }
}

extern "C" void kernel_launch(void* const* d_in, const int* in_sizes, int n_in,
                              void* d_out, int out_size)
{
    const float4* loc_data  = nullptr;
    const float4* loc_tgt   = nullptr;
    const float2* conf_data = nullptr;
    const int2*   conf_tgt  = nullptr;
    for (int i = 0; i < n_in; i++) {
        if (in_sizes[i] == B_DIM * D_DIM * 4) {
            if (!loc_data) loc_data = (const float4*)d_in[i];
            else           loc_tgt  = (const float4*)d_in[i];
        } else {
            if (!conf_data) conf_data = (const float2*)d_in[i];
            else            conf_tgt  = (const int2*)d_in[i];
        }
    }

    mbl_pass1<<<B_DIM * S_SL, NTA>>>(loc_data, conf_data, loc_tgt, conf_tgt);
    mbl_select<<<B_DIM, NTB>>>();
    mbl_fin<<<1, 64>>>((float*)d_out);
}

// round 5
// speedup vs baseline: 1.6160x; 1.1346x over previous
#include <cuda_runtime.h>
#include <math.h>

#define B_DIM 64
#define D_DIM 65536
#define S_SL  8
#define NTA   512
#define SLICE (D_DIM / S_SL)
#define PAIRS_T (SLICE / 2 / NTA)    // 8
#define NTB   1024
#define CAP   2048
#define BIAS  6000                   // bin 0 <-> x = 2^-8 ; 16 bins per octave
#define SAFE_BIN 128                 // bin 128 <-> x = 1.0

// ---- __device__ scratch (allocation-free, fully overwritten each launch) ----
__device__ unsigned short g_bins16[B_DIM * D_DIM / 2];   // 4MB: 2 packed u8 bins
__device__ unsigned g_hist[B_DIM * S_SL * 256];
__device__ float    g_hsum[B_DIM * S_SL * 256];
__device__ float    g_sl_loc[B_DIM * S_SL];
__device__ float    g_sl_bce[B_DIM * S_SL];
__device__ int      g_sl_pos[B_DIM * S_SL];
__device__ float    g_row_loc[B_DIM];
__device__ float    g_row_conf[B_DIM];
__device__ int      g_row_pos[B_DIM];
__device__ int      g_row_sel[B_DIM];

__device__ __forceinline__ float softplus_f(float x) {
    return fmaxf(x, 0.0f) + log1pf(expf(-fabsf(x)));
}
__device__ __forceinline__ float sl1f(float d) {
    float ad = fabsf(d);
    return (ad < 1.0f) ? 0.5f * d * d : (ad - 0.5f);
}
__device__ __forceinline__ unsigned key_of(float x) {
    unsigned u = __float_as_uint(x);
    return (u & 0x80000000u) ? ~u : (u | 0x80000000u);
}
__device__ __forceinline__ float val_of_key(unsigned k) {
    unsigned u = (k & 0x80000000u) ? (k & 0x7FFFFFFFu) : ~k;
    return __uint_as_float(u);
}
__device__ __forceinline__ int bin_of(unsigned key) {
    return min(255, max(0, (int)(key >> 19) - BIAS));
}

template<int NWARP>
__device__ __forceinline__ float blk_sum(float v, float* red, int t) {
    #pragma unroll
    for (int o = 16; o > 0; o >>= 1) v += __shfl_down_sync(0xFFFFFFFFu, v, o);
    if ((t & 31) == 0) red[t >> 5] = v;
    __syncthreads();
    if (t < 32) {
        float w = (t < NWARP) ? red[t] : 0.0f;
        #pragma unroll
        for (int o = 16; o > 0; o >>= 1) w += __shfl_down_sync(0xFFFFFFFFu, w, o);
        if (t == 0) red[0] = w;
    }
    __syncthreads();
    float r = red[0];
    __syncthreads();
    return r;
}

// Warp-cooperative descending select over 256 bins (lanes 0..31), exact.
__device__ __forceinline__ int warp_select(const unsigned* h, int k, int lane, int* rem_out) {
    int s = 0;
    #pragma unroll
    for (int m = 0; m < 8; m++) s += (int)h[255 - lane * 8 - m];
    int inc = s;
    #pragma unroll
    for (int o = 1; o < 32; o <<= 1) {
        int v = __shfl_up_sync(0xFFFFFFFFu, inc, o);
        if (lane >= o) inc += v;
    }
    int pre = inc - s;
    unsigned m = __ballot_sync(0xFFFFFFFFu, (pre < k) && (pre + s >= k));
    int chosen = __ffs(m) - 1;
    int bin = 0, rem = 0;
    if (lane == chosen) {
        int acc = pre, hi = 255 - lane * 8;
        #pragma unroll
        for (int b = 0; b < 8; b++) {
            int c = (int)h[hi - b];
            if (acc + c >= k) { bin = hi - b; rem = k - acc; break; }
            acc += c;
        }
    }
    bin = __shfl_sync(0xFFFFFFFFu, bin, chosen);
    rem = __shfl_sync(0xFFFFFFFFu, rem, chosen);
    *rem_out = rem;
    return bin;
}

// -------- Pass 1: stats + per-element bin byte + per-bin counts & sp-sums --------
__global__ void __launch_bounds__(NTA) mbl_pass1(
    const float4* __restrict__ loc_data,
    const float2* __restrict__ conf2,
    const float4* __restrict__ loc_t,
    const int2*   __restrict__ ct2)
{
    __shared__ unsigned wh[16][256];   // warp-private counts (16KB)
    __shared__ float    ws[16][256];   // warp-private sp-sums (16KB)
    __shared__ float    red[16];

    const int t = threadIdx.x, w = t >> 5;
    const int row = blockIdx.x / S_SL, sl = blockIdx.x % S_SL;

    for (int i = t; i < 16 * 256; i += NTA) { ((unsigned*)wh)[i] = 0; ((float*)ws)[i] = 0.0f; }
    __syncthreads();

    const size_t pq0 = (size_t)row * (D_DIM / 2) + (size_t)sl * (SLICE / 2);
    float npos = 0.0f, pb = 0.0f, ls = 0.0f;

    #pragma unroll
    for (int j = 0; j < PAIRS_T; j++) {
        size_t q = pq0 + t + (size_t)j * NTA;
        float2 x = conf2[q];
        int2   c = ct2[q];
        size_t e = 2 * q;
        unsigned b0 = 0u, b1 = 0u;
        if (c.x > 0) {
            npos += 1.0f; pb += softplus_f(-x.x);
            float4 a = loc_data[e], b = loc_t[e];
            ls += sl1f(a.x - b.x) + sl1f(a.y - b.y) + sl1f(a.z - b.z) + sl1f(a.w - b.w);
        } else {
            int bin = bin_of(key_of(x.x));
            b0 = (unsigned)bin;
            atomicAdd(&wh[w][bin], 1u);
            if (bin >= SAFE_BIN) atomicAdd(&ws[w][bin], softplus_f(x.x));
        }
        if (c.y > 0) {
            npos += 1.0f; pb += softplus_f(-x.y);
            float4 a = loc_data[e + 1], b = loc_t[e + 1];
            ls += sl1f(a.x - b.x) + sl1f(a.y - b.y) + sl1f(a.z - b.z) + sl1f(a.w - b.w);
        } else {
            int bin = bin_of(key_of(x.y));
            b1 = (unsigned)bin;
            atomicAdd(&wh[w][bin], 1u);
            if (bin >= SAFE_BIN) atomicAdd(&ws[w][bin], softplus_f(x.y));
        }
        g_bins16[q] = (unsigned short)(b0 | (b1 << 8));
    }
    __syncthreads();

    if (t < 256) {
        unsigned s = 0;
        #pragma unroll
        for (int m = 0; m < 16; m++) s += wh[m][t];
        g_hist[blockIdx.x * 256 + t] = s;
    } else {
        int b = t - 256;
        float s = 0.0f;
        #pragma unroll
        for (int m = 0; m < 16; m++) s += ws[m][b];
        g_hsum[blockIdx.x * 256 + b] = s;
    }

    float npos_r = blk_sum<16>(npos, red, t);
    float ls_r   = blk_sum<16>(ls,   red, t);
    float pb_r   = blk_sum<16>(pb,   red, t);
    if (t == 0) {
        g_sl_pos[blockIdx.x] = (int)npos_r;
        g_sl_loc[blockIdx.x] = ls_r;
        g_sl_bce[blockIdx.x] = pb_r;
    }
}

// -------- Pass 2: per-row select; strict part from bin sums, boundary exact --------
__global__ void __launch_bounds__(NTB) mbl_select(
    const float* __restrict__ conf,
    const float2* __restrict__ conf2,
    const int2*   __restrict__ ct2)
{
    __shared__ unsigned h[256];
    __shared__ float    hs[256];
    __shared__ unsigned rh[256];
    __shared__ unsigned list[CAP];
    __shared__ float    red[32];
    __shared__ int      sh_b8, sh_rem, sh_nlist, sh_bin2, sh_rem2, sh_npos, sh_k;
    __shared__ float    sh_pb, sh_ls;

    const int t = threadIdx.x;
    const int row = blockIdx.x;

    if (t < 256) {
        unsigned s = 0;
        #pragma unroll
        for (int m = 0; m < S_SL; m++) s += g_hist[(row * S_SL + m) * 256 + t];
        h[t] = s;
    } else if (t < 512) {
        int b = t - 256;
        float s = 0.0f;
        #pragma unroll
        for (int m = 0; m < S_SL; m++) s += g_hsum[(row * S_SL + m) * 256 + b];
        hs[b] = s;
    }
    if (t == 0) {
        int np = 0; float pb = 0.0f, ls = 0.0f;
        #pragma unroll
        for (int m = 0; m < S_SL; m++) {
            np += g_sl_pos[row * S_SL + m];
            pb += g_sl_bce[row * S_SL + m];
            ls += g_sl_loc[row * S_SL + m];
        }
        sh_npos = np; sh_pb = pb; sh_ls = ls;
        sh_k = min(3 * np, D_DIM);
        sh_nlist = 0;
    }
    __syncthreads();
    const int k = sh_k;

    if (t < 32) {
        if (k > 0) {
            int rem; int b = warp_select(h, k, t, &rem);
            if (t == 0) { sh_b8 = b; sh_rem = rem; }
        } else if (t == 0) { sh_b8 = -1; sh_rem = 0; }
    }
    __syncthreads();
    const int b8 = sh_b8;
    const bool fast = (k > 0) && (b8 >= SAFE_BIN) && (b8 < 255);

    float csum = 0.0f;
    unsigned T = 0u; int req = 0;

    if (fast) {
        if (t < 256 && t > b8) csum += hs[t];   // strict part, no scan needed

        // scan this row's 64KB of bin bytes, gather boundary elements
        const uint4* bp = reinterpret_cast<const uint4*>(g_bins16) + (size_t)row * (D_DIM / 16);
        const unsigned rep = (unsigned)b8 * 0x01010101u;
        #pragma unroll
        for (int jj = 0; jj < D_DIM / 16 / NTB; jj++) {    // 4 iterations
            int i4 = t + jj * NTB;
            uint4 wv = bp[i4];
            unsigned wd[4] = {wv.x, wv.y, wv.z, wv.w};
            #pragma unroll
            for (int wi = 0; wi < 4; wi++) {
                unsigned x = wd[wi] ^ rep;
                if ((x - 0x01010101u) & ~x & 0x80808080u) {
                    #pragma unroll
                    for (int bi = 0; bi < 4; bi++) {
                        if (((wd[wi] >> (8 * bi)) & 255u) == (unsigned)b8) {
                            int idx = i4 * 16 + wi * 4 + bi;
                            int p = atomicAdd(&sh_nlist, 1);
                            if (p < CAP) list[p] = key_of(conf[(size_t)row * D_DIM + idx]);
                        }
                    }
                }
            }
        }
    }
    __syncthreads();
    const int nlist = sh_nlist;

    if (fast && nlist <= CAP) {
        // exact refine of bits [18:0] within the boundary bin, all in shared
        int rem = sh_rem;
        unsigned c1 = 0, c2 = 0, c3 = 0;
        // level A: bits [18:11]
        if (t < 256) rh[t] = 0;
        __syncthreads();
        for (int p = t; p < nlist; p += NTB) atomicAdd(&rh[(list[p] >> 11) & 255u], 1u);
        __syncthreads();
        if (t < 32) { int r; int b = warp_select(rh, rem, t, &r); if (t == 0) { sh_bin2 = b; sh_rem2 = r; } }
        __syncthreads();
        c1 = (unsigned)sh_bin2; rem = sh_rem2;
        __syncthreads();
        // level B: bits [10:3]
        if (t < 256) rh[t] = 0;
        __syncthreads();
        for (int p = t; p < nlist; p += NTB) {
            unsigned kk = list[p];
            if (((kk >> 11) & 255u) == c1) atomicAdd(&rh[(kk >> 3) & 255u], 1u);
        }
        __syncthreads();
        if (t < 32) { int r; int b = warp_select(rh, rem, t, &r); if (t == 0) { sh_bin2 = b; sh_rem2 = r; } }
        __syncthreads();
        c2 = (unsigned)sh_bin2; rem = sh_rem2;
        __syncthreads();
        // level C: bits [2:0]
        if (t < 256) rh[t] = 0;
        __syncthreads();
        for (int p = t; p < nlist; p += NTB) {
            unsigned kk = list[p];
            if (((kk >> 11) & 255u) == c1 && ((kk >> 3) & 255u) == c2)
                atomicAdd(&rh[kk & 7u], 1u);
        }
        __syncthreads();
        if (t < 32) { int r; int b = warp_select(rh, rem, t, &r); if (t == 0) { sh_bin2 = b; sh_rem2 = r; } }
        __syncthreads();
        c3 = (unsigned)sh_bin2; req = sh_rem2;

        T = ((unsigned)(b8 + BIAS) << 19) | (c1 << 11) | (c2 << 3) | c3;
        for (int p = t; p < nlist; p += NTB) {
            unsigned kk = list[p];
            if (kk > T) csum += softplus_f(val_of_key(kk));
        }
    } else if (k > 0) {
        // ---- full fallback: exact radix select recomputing keys from conf/ct ----
        csum = 0.0f;
        const size_t pr0 = (size_t)row * (D_DIM / 2);
        unsigned prefix = 0u; int rem = k;
        for (int lvl = 0; lvl < 4; lvl++) {
            if (t < 256) rh[t] = 0;
            __syncthreads();
            for (int j = 0; j < (D_DIM / 2) / NTB; j++) {
                size_t q = pr0 + t + (size_t)j * NTB;
                float2 x = conf2[q]; int2 c = ct2[q];
                if (c.x <= 0) {
                    unsigned kk = key_of(x.x);
                    if (lvl == 0 || (kk >> (32 - 8 * lvl)) == prefix)
                        atomicAdd(&rh[(kk >> (24 - 8 * lvl)) & 255u], 1u);
                }
                if (c.y <= 0) {
                    unsigned kk = key_of(x.y);
                    if (lvl == 0 || (kk >> (32 - 8 * lvl)) == prefix)
                        atomicAdd(&rh[(kk >> (24 - 8 * lvl)) & 255u], 1u);
                }
            }
            __syncthreads();
            if (t < 32) { int r; int b = warp_select(rh, rem, t, &r); if (t == 0) { sh_bin2 = b; sh_rem2 = r; } }
            __syncthreads();
            prefix = (prefix << 8) | (unsigned)sh_bin2;
            rem = sh_rem2;
            __syncthreads();
        }
        T = prefix; req = rem;
        for (int j = 0; j < (D_DIM / 2) / NTB; j++) {
            size_t q = pr0 + t + (size_t)j * NTB;
            float2 x = conf2[q]; int2 c = ct2[q];
            if (c.x <= 0 && key_of(x.x) > T) csum += softplus_f(x.x);
            if (c.y <= 0 && key_of(x.y) > T) csum += softplus_f(x.y);
        }
    }
    __syncthreads();

    float csum_row = blk_sum<32>(csum, red, t);
    if (t == 0) {
        float tv = (req > 0) ? softplus_f(val_of_key(T)) : 0.0f;
        g_row_conf[row] = sh_pb + csum_row + (float)req * tv;
        g_row_loc[row]  = sh_ls;
        g_row_pos[row]  = sh_npos;
        g_row_sel[row]  = sh_npos + k;
    }
}

__global__ void mbl_fin(float* out) {
    int t = threadIdx.x;   // 64 threads
    float lc = g_row_loc[t], cf = g_row_conf[t];
    float ps = (float)g_row_pos[t], sl = (float)g_row_sel[t];
    #pragma unroll
    for (int o = 16; o > 0; o >>= 1) {
        lc += __shfl_down_sync(0xFFFFFFFFu, lc, o);
        cf += __shfl_down_sync(0xFFFFFFFFu, cf, o);
        ps += __shfl_down_sync(0xFFFFFFFFu, ps, o);
        sl += __shfl_down_sync(0xFFFFFFFFu, sl, o);
    }
    __shared__ float sh[8];
    if ((t & 31) == 0) {
        int w = t >> 5;
        sh[w * 4 + 0] = lc; sh[w * 4 + 1] = cf; sh[w * 4 + 2] = ps; sh[w * 4 + 3] = sl;
    }
    __syncthreads();
    if (t == 0) {
        lc = sh[0] + sh[4]; cf = sh[1] + sh[5];
        ps = sh[2] + sh[6]; sl = sh[3] + sh[7];
        out[0] = lc / (4.0f * ps) / ps;
        out[1] = cf / sl / ps;
    }
}

extern "C" void kernel_launch(void* const* d_in, const int* in_sizes, int n_in,
                              void* d_out, int out_size)
{
    const float4* loc_data  = nullptr;
    const float4* loc_tgt   = nullptr;
    const float*  conf_data = nullptr;
    const int*    conf_tgt  = nullptr;
    for (int i = 0; i < n_in; i++) {
        if (in_sizes[i] == B_DIM * D_DIM * 4) {
            if (!loc_data) loc_data = (const float4*)d_in[i];
            else           loc_tgt  = (const float4*)d_in[i];
        } else {
            if (!conf_data) conf_data = (const float*)d_in[i];
            else            conf_tgt  = (const int*)d_in[i];
        }
    }

    mbl_pass1<<<B_DIM * S_SL, NTA>>>(loc_data, (const float2*)conf_data,
                                     loc_tgt, (const int2*)conf_tgt);
    mbl_select<<<B_DIM, NTB>>>(conf_data, (const float2*)conf_data,
                               (const int2*)conf_tgt);
    mbl_fin<<<1, 64>>>((float*)d_out);
}

// round 6
// speedup vs baseline: 1.6460x; 1.0185x over previous
#include <cuda_runtime.h>
#include <math.h>

#define B_DIM 64
#define D_DIM 65536
#define S_SL  8
#define NTA   512
#define SLICE (D_DIM / S_SL)
#define PAIRS_T (SLICE / 2 / NTA)    // 8
#define NTB   1024
#define CAP   2048
#define BIAS  6000                   // bin = (key>>19) - BIAS ; 16 bins per octave
#define SAFE_BIN 128                 // bin 128 <-> x = 1.0 ; histogram only >= this
#define NB    128                    // tracked bins (128..255)

// ---- __device__ scratch (allocation-free; fully overwritten / self-resetting) ----
__device__ unsigned short g_bins16[B_DIM * D_DIM / 2];   // 4MB packed u8 bins (0 if <128)
__device__ unsigned g_hist[B_DIM * S_SL * NB];
__device__ float    g_hsum[B_DIM * S_SL * NB];
__device__ float    g_sl_loc[B_DIM * S_SL];
__device__ float    g_sl_bce[B_DIM * S_SL];
__device__ int      g_sl_pos[B_DIM * S_SL];
__device__ float    g_row_loc[B_DIM];
__device__ float    g_row_conf[B_DIM];
__device__ int      g_row_pos[B_DIM];
__device__ int      g_row_sel[B_DIM];
__device__ int      g_ctr;                               // last-CTA counter (self-reset)

__device__ __forceinline__ float softplus_f(float x) {
    return fmaxf(x, 0.0f) + log1pf(expf(-fabsf(x)));
}
__device__ __forceinline__ float sl1f(float d) {
    float ad = fabsf(d);
    return (ad < 1.0f) ? 0.5f * d * d : (ad - 0.5f);
}
__device__ __forceinline__ unsigned key_of(float x) {
    unsigned u = __float_as_uint(x);
    return (u & 0x80000000u) ? ~u : (u | 0x80000000u);
}
__device__ __forceinline__ float val_of_key(unsigned k) {
    unsigned u = (k & 0x80000000u) ? (k & 0x7FFFFFFFu) : ~k;
    return __uint_as_float(u);
}
__device__ __forceinline__ int bin_of(unsigned key) {
    return min(255, max(0, (int)(key >> 19) - BIAS));
}

template<int NWARP>
__device__ __forceinline__ float blk_sum(float v, float* red, int t) {
    #pragma unroll
    for (int o = 16; o > 0; o >>= 1) v += __shfl_down_sync(0xFFFFFFFFu, v, o);
    if ((t & 31) == 0) red[t >> 5] = v;
    __syncthreads();
    if (t < 32) {
        float w = (t < NWARP) ? red[t] : 0.0f;
        #pragma unroll
        for (int o = 16; o > 0; o >>= 1) w += __shfl_down_sync(0xFFFFFFFFu, w, o);
        if (t == 0) red[0] = w;
    }
    __syncthreads();
    float r = red[0];
    __syncthreads();
    return r;
}

// Warp-cooperative descending select over NBINS bins (lanes 0..31).
template<int NBINS>
__device__ __forceinline__ int warp_select(const unsigned* h, int k, int lane, int* rem_out) {
    const int PER = NBINS / 32;
    int s = 0;
    #pragma unroll
    for (int m = 0; m < PER; m++) s += (int)h[NBINS - 1 - lane * PER - m];
    int inc = s;
    #pragma unroll
    for (int o = 1; o < 32; o <<= 1) {
        int v = __shfl_up_sync(0xFFFFFFFFu, inc, o);
        if (lane >= o) inc += v;
    }
    int pre = inc - s;
    unsigned m = __ballot_sync(0xFFFFFFFFu, (pre < k) && (pre + s >= k));
    int chosen = __ffs(m) - 1;
    int bin = 0, rem = 0;
    if (lane == chosen) {
        int acc = pre, hi = NBINS - 1 - lane * PER;
        #pragma unroll
        for (int b = 0; b < PER; b++) {
            int c = (int)h[hi - b];
            if (acc + c >= k) { bin = hi - b; rem = k - acc; break; }
            acc += c;
        }
    }
    bin = __shfl_sync(0xFFFFFFFFu, bin, chosen);
    rem = __shfl_sync(0xFFFFFFFFu, rem, chosen);
    *rem_out = rem;
    return bin;
}

// -------- Pass 1: stats + bin bytes + gated (bin>=128) counts & sp-sums --------
__global__ void __launch_bounds__(NTA) mbl_pass1(
    const float4* __restrict__ loc_data,
    const float2* __restrict__ conf2,
    const float4* __restrict__ loc_t,
    const int2*   __restrict__ ct2)
{
    __shared__ unsigned wh[16][NB];   // 8KB warp-private counts (bins 128..255)
    __shared__ float    ws[16][NB];   // 8KB warp-private sp-sums
    __shared__ float    red[16];

    const int t = threadIdx.x, w = t >> 5;
    const int row = blockIdx.x / S_SL, sl = blockIdx.x % S_SL;

    for (int i = t; i < 16 * NB; i += NTA) { ((unsigned*)wh)[i] = 0; ((float*)ws)[i] = 0.0f; }
    __syncthreads();

    const size_t pq0 = (size_t)row * (D_DIM / 2) + (size_t)sl * (SLICE / 2);
    float npos = 0.0f, pb = 0.0f, ls = 0.0f;

    #pragma unroll
    for (int j = 0; j < PAIRS_T; j++) {
        size_t q = pq0 + t + (size_t)j * NTA;
        float2 x = conf2[q];
        int2   c = ct2[q];
        size_t e = 2 * q;
        unsigned b0 = 0u, b1 = 0u;
        if (c.x > 0) {
            npos += 1.0f; pb += softplus_f(-x.x);
            float4 a = loc_data[e], b = loc_t[e];
            ls += sl1f(a.x - b.x) + sl1f(a.y - b.y) + sl1f(a.z - b.z) + sl1f(a.w - b.w);
        } else {
            int bin = bin_of(key_of(x.x));
            if (bin >= SAFE_BIN) {          // ~6% of elements only
                b0 = (unsigned)bin;
                atomicAdd(&wh[w][bin - SAFE_BIN], 1u);
                atomicAdd(&ws[w][bin - SAFE_BIN], softplus_f(x.x));
            }
        }
        if (c.y > 0) {
            npos += 1.0f; pb += softplus_f(-x.y);
            float4 a = loc_data[e + 1], b = loc_t[e + 1];
            ls += sl1f(a.x - b.x) + sl1f(a.y - b.y) + sl1f(a.z - b.z) + sl1f(a.w - b.w);
        } else {
            int bin = bin_of(key_of(x.y));
            if (bin >= SAFE_BIN) {
                b1 = (unsigned)bin;
                atomicAdd(&wh[w][bin - SAFE_BIN], 1u);
                atomicAdd(&ws[w][bin - SAFE_BIN], softplus_f(x.y));
            }
        }
        g_bins16[q] = (unsigned short)(b0 | (b1 << 8));
    }
    __syncthreads();

    if (t < NB) {
        unsigned s = 0;
        #pragma unroll
        for (int m = 0; m < 16; m++) s += wh[m][t];
        g_hist[blockIdx.x * NB + t] = s;
    } else if (t < 2 * NB) {
        int b = t - NB;
        float s = 0.0f;
        #pragma unroll
        for (int m = 0; m < 16; m++) s += ws[m][b];
        g_hsum[blockIdx.x * NB + b] = s;
    }

    float npos_r = blk_sum<16>(npos, red, t);
    float ls_r   = blk_sum<16>(ls,   red, t);
    float pb_r   = blk_sum<16>(pb,   red, t);
    if (t == 0) {
        g_sl_pos[blockIdx.x] = (int)npos_r;
        g_sl_loc[blockIdx.x] = ls_r;
        g_sl_bce[blockIdx.x] = pb_r;
    }
}

// -------- Pass 2: per-row select + final reduction (last CTA) --------
__global__ void __launch_bounds__(NTB) mbl_select(
    const float*  __restrict__ conf,
    const float2* __restrict__ conf2,
    const int2*   __restrict__ ct2,
    float* __restrict__ out)
{
    __shared__ unsigned h[NB];
    __shared__ float    hs[NB];
    __shared__ unsigned rh[256];
    __shared__ unsigned list[CAP];
    __shared__ float    red[32];
    __shared__ int      sh_ib, sh_rem, sh_nlist, sh_bin2, sh_rem2, sh_npos, sh_k, sh_tot;
    __shared__ float    sh_pb, sh_ls;
    __shared__ int      sh_last;

    const int t = threadIdx.x;
    const int row = blockIdx.x;

    if (t < NB) {
        unsigned s = 0;
        #pragma unroll
        for (int m = 0; m < S_SL; m++) s += g_hist[(row * S_SL + m) * NB + t];
        h[t] = s;
    } else if (t < 2 * NB) {
        int b = t - NB;
        float s = 0.0f;
        #pragma unroll
        for (int m = 0; m < S_SL; m++) s += g_hsum[(row * S_SL + m) * NB + b];
        hs[b] = s;
    }
    if (t == 0) {
        int np = 0; float pb = 0.0f, ls = 0.0f;
        #pragma unroll
        for (int m = 0; m < S_SL; m++) {
            np += g_sl_pos[row * S_SL + m];
            pb += g_sl_bce[row * S_SL + m];
            ls += g_sl_loc[row * S_SL + m];
        }
        sh_npos = np; sh_pb = pb; sh_ls = ls;
        sh_k = min(3 * np, D_DIM);
        sh_nlist = 0;
    }
    __syncthreads();
    const int k = sh_k;

    if (t < 32) {
        int s = 0;
        #pragma unroll
        for (int m = 0; m < 4; m++) s += (int)h[t * 4 + m];
        #pragma unroll
        for (int o = 16; o > 0; o >>= 1) s += __shfl_down_sync(0xFFFFFFFFu, s, o);
        if (t == 0) sh_tot = s;
        __syncwarp();
        int tot = __shfl_sync(0xFFFFFFFFu, sh_tot, 0);
        if (k > 0 && tot >= k) {
            int rem; int ib = warp_select<NB>(h, k, t, &rem);
            if (t == 0) { sh_ib = ib; sh_rem = rem; }
        } else if (t == 0) sh_ib = -1;
    }
    __syncthreads();
    const int ib = sh_ib;                      // boundary index (bin = 128+ib)
    const int b8 = SAFE_BIN + ib;
    const bool fast = (k > 0) && (ib >= 0) && (ib < NB - 1);

    float csum = 0.0f;
    unsigned T = 0u; int req = 0;

    if (fast) {
        if (t < NB && t > ib) csum += hs[t];   // strict part from per-bin sums

        // scan 64KB of bin bytes; gather boundary-bin logits
        const uint4* bp = reinterpret_cast<const uint4*>(g_bins16) + (size_t)row * (D_DIM / 16);
        const unsigned rep = (unsigned)b8 * 0x01010101u;
        #pragma unroll
        for (int jj = 0; jj < D_DIM / 16 / NTB; jj++) {
            int i4 = t + jj * NTB;
            uint4 wv = bp[i4];
            unsigned wd[4] = {wv.x, wv.y, wv.z, wv.w};
            #pragma unroll
            for (int wi = 0; wi < 4; wi++) {
                unsigned x = wd[wi] ^ rep;
                if ((x - 0x01010101u) & ~x & 0x80808080u) {
                    #pragma unroll
                    for (int bi = 0; bi < 4; bi++) {
                        if (((wd[wi] >> (8 * bi)) & 255u) == (unsigned)b8) {
                            int idx = i4 * 16 + wi * 4 + bi;
                            int p = atomicAdd(&sh_nlist, 1);
                            if (p < CAP) list[p] = key_of(conf[(size_t)row * D_DIM + idx]);
                        }
                    }
                }
            }
        }
    }
    __syncthreads();
    const int nlist = sh_nlist;

    if (fast && nlist <= CAP) {
        // exact refine of key bits [18:0], all in shared
        int rem = sh_rem;
        unsigned c1, c2, c3;
        if (t < 256) rh[t] = 0;
        __syncthreads();
        for (int p = t; p < nlist; p += NTB) atomicAdd(&rh[(list[p] >> 11) & 255u], 1u);
        __syncthreads();
        if (t < 32) { int r; int b = warp_select<256>(rh, rem, t, &r); if (t == 0) { sh_bin2 = b; sh_rem2 = r; } }
        __syncthreads();
        c1 = (unsigned)sh_bin2; rem = sh_rem2;
        __syncthreads();
        if (t < 256) rh[t] = 0;
        __syncthreads();
        for (int p = t; p < nlist; p += NTB) {
            unsigned kk = list[p];
            if (((kk >> 11) & 255u) == c1) atomicAdd(&rh[(kk >> 3) & 255u], 1u);
        }
        __syncthreads();
        if (t < 32) { int r; int b = warp_select<256>(rh, rem, t, &r); if (t == 0) { sh_bin2 = b; sh_rem2 = r; } }
        __syncthreads();
        c2 = (unsigned)sh_bin2; rem = sh_rem2;
        __syncthreads();
        if (t < 256) rh[t] = 0;
        __syncthreads();
        for (int p = t; p < nlist; p += NTB) {
            unsigned kk = list[p];
            if (((kk >> 11) & 255u) == c1 && ((kk >> 3) & 255u) == c2)
                atomicAdd(&rh[kk & 7u], 1u);
        }
        __syncthreads();
        if (t < 32) { int r; int b = warp_select<256>(rh, rem, t, &r); if (t == 0) { sh_bin2 = b; sh_rem2 = r; } }
        __syncthreads();
        c3 = (unsigned)sh_bin2; req = sh_rem2;

        T = ((unsigned)(b8 + BIAS) << 19) | (c1 << 11) | (c2 << 3) | c3;
        for (int p = t; p < nlist; p += NTB) {
            unsigned kk = list[p];
            if (kk > T) csum += softplus_f(val_of_key(kk));
        }
    } else if (k > 0) {
        // exact fallback: 4-level radix select recomputing keys from conf/ct
        csum = 0.0f;
        const size_t pr0 = (size_t)row * (D_DIM / 2);
        unsigned prefix = 0u; int rem = k;
        for (int lvl = 0; lvl < 4; lvl++) {
            if (t < 256) rh[t] = 0;
            __syncthreads();
            for (int j = 0; j < (D_DIM / 2) / NTB; j++) {
                size_t q = pr0 + t + (size_t)j * NTB;
                float2 x = conf2[q]; int2 c = ct2[q];
                if (c.x <= 0) {
                    unsigned kk = key_of(x.x);
                    if (lvl == 0 || (kk >> (32 - 8 * lvl)) == prefix)
                        atomicAdd(&rh[(kk >> (24 - 8 * lvl)) & 255u], 1u);
                }
                if (c.y <= 0) {
                    unsigned kk = key_of(x.y);
                    if (lvl == 0 || (kk >> (32 - 8 * lvl)) == prefix)
                        atomicAdd(&rh[(kk >> (24 - 8 * lvl)) & 255u], 1u);
                }
            }
            __syncthreads();
            if (t < 32) { int r; int b = warp_select<256>(rh, rem, t, &r); if (t == 0) { sh_bin2 = b; sh_rem2 = r; } }
            __syncthreads();
            prefix = (prefix << 8) | (unsigned)sh_bin2;
            rem = sh_rem2;
            __syncthreads();
        }
        T = prefix; req = rem;
        for (int j = 0; j < (D_DIM / 2) / NTB; j++) {
            size_t q = pr0 + t + (size_t)j * NTB;
            float2 x = conf2[q]; int2 c = ct2[q];
            if (c.x <= 0 && key_of(x.x) > T) csum += softplus_f(x.x);
            if (c.y <= 0 && key_of(x.y) > T) csum += softplus_f(x.y);
        }
    }
    __syncthreads();

    float csum_row = blk_sum<32>(csum, red, t);
    if (t == 0) {
        float tv = (req > 0) ? softplus_f(val_of_key(T)) : 0.0f;
        g_row_conf[row] = sh_pb + csum_row + (float)req * tv;
        g_row_loc[row]  = sh_ls;
        g_row_pos[row]  = sh_npos;
        g_row_sel[row]  = sh_npos + k;
        __threadfence();
        int v = atomicAdd(&g_ctr, 1);
        sh_last = (v == B_DIM - 1) ? 1 : 0;
    }
    __syncthreads();

    // last CTA performs the final cross-row reduction (replaces mbl_fin)
    if (sh_last) {
        __threadfence();
        if (t == 0) g_ctr = 0;           // self-reset for next graph replay
        if (t < 64) {
            float lc = g_row_loc[t], cf = g_row_conf[t];
            float ps = (float)g_row_pos[t], sl = (float)g_row_sel[t];
            #pragma unroll
            for (int o = 16; o > 0; o >>= 1) {
                lc += __shfl_down_sync(0xFFFFFFFFu, lc, o);
                cf += __shfl_down_sync(0xFFFFFFFFu, cf, o);
                ps += __shfl_down_sync(0xFFFFFFFFu, ps, o);
                sl += __shfl_down_sync(0xFFFFFFFFu, sl, o);
            }
            if ((t & 31) == 0) {
                red[(t >> 5) * 4 + 0] = lc; red[(t >> 5) * 4 + 1] = cf;
                red[(t >> 5) * 4 + 2] = ps; red[(t >> 5) * 4 + 3] = sl;
            }
        }
        __syncthreads();
        if (t == 0) {
            float lc = red[0] + red[4], cf = red[1] + red[5];
            float ps = red[2] + red[6], sl = red[3] + red[7];
            out[0] = lc / (4.0f * ps) / ps;
            out[1] = cf / sl / ps;
        }
    }
}

extern "C" void kernel_launch(void* const* d_in, const int* in_sizes, int n_in,
                              void* d_out, int out_size)
{
    const float4* loc_data  = nullptr;
    const float4* loc_tgt   = nullptr;
    const float*  conf_data = nullptr;
    const int*    conf_tgt  = nullptr;
    for (int i = 0; i < n_in; i++) {
        if (in_sizes[i] == B_DIM * D_DIM * 4) {
            if (!loc_data) loc_data = (const float4*)d_in[i];
            else           loc_tgt  = (const float4*)d_in[i];
        } else {
            if (!conf_data) conf_data = (const float*)d_in[i];
            else            conf_tgt  = (const int*)d_in[i];
        }
    }

    mbl_pass1<<<B_DIM * S_SL, NTA>>>(loc_data, (const float2*)conf_data,
                                     loc_tgt, (const int2*)conf_tgt);
    mbl_select<<<B_DIM, NTB>>>(conf_data, (const float2*)conf_data,
                               (const int2*)conf_tgt, (float*)d_out);
}